// round 1
// baseline (speedup 1.0000x reference)
#include <cuda_runtime.h>
#include <math.h>

#define NN 50000
#define EE 800000
#define HH 32
#define GG 64

// -------- scratch (device globals; allocation-free) --------
static __device__ float g_acc1[NN * 128];   // layer-1 scatter accumulator (N,4,H)
static __device__ float g_h1[NN * 128];     // after norm_act(dw(.,si1))
static __device__ float g_acc2[NN * 128];   // layer-2 scatter accumulator
static __device__ float g_h2[NN * 128];     // after norm_act(dw(.,si2))
static __device__ float g_acc3[NN * 32];    // layer-3 scatter accumulator (N,1,H)
static __device__ float g_pool[GG * 32];    // pooled per-graph

// -------- helpers --------
__device__ __forceinline__ void red4(float* p, float a, float b, float c, float d) {
    asm volatile("red.global.add.v4.f32 [%0], {%1,%2,%3,%4};"
                 :: "l"(p), "f"(a), "f"(b), "f"(c), "f"(d) : "memory");
}

__device__ __forceinline__ float sspf(float x) {   // softplus(x) - ln2, x >= 0
    return x + log1pf(__expf(-x)) - 0.6931471805599453f;
}

__device__ __forceinline__ void edge_basis(float d, float* emb, float& ew) {
    #pragma unroll
    for (int k = 0; k < 10; k++) {
        float mu = 0.7f + (float)k * (1.0f / 9.0f);
        float t = d - mu;
        emb[k] = __expf(-t * t * 50.0f);     // sigma=0.1 -> 1/(2*0.01)=50
    }
    float u = d * (1.0f / 1.5f);
    float u2 = u * u, u3 = u2 * u, u6 = u3 * u3;
    float f = 1.0f - 28.0f * u6 + 48.0f * u6 * u - 21.0f * u6 * u2;
    ew = (u < 1.0f) ? f : 0.0f;
}

// -------- zero accumulators --------
__global__ void k_zero() {
    size_t i = (size_t)blockIdx.x * blockDim.x + threadIdx.x;
    size_t stride = (size_t)gridDim.x * blockDim.x;
    float4 z = make_float4(0.f, 0.f, 0.f, 0.f);
    for (size_t j = i; j < (size_t)NN * 32; j += stride) {
        ((float4*)g_acc1)[j] = z;
        ((float4*)g_acc2)[j] = z;
    }
    for (size_t j = i; j < (size_t)NN * 8; j += stride) ((float4*)g_acc3)[j] = z;
    for (size_t j = i; j < (size_t)GG * 8; j += stride) ((float4*)g_pool)[j] = z;
}

// -------- layer 1 edge kernel --------
// warp = 4 edges; lane: sub = lane>>3 selects edge, h0 = 4*(lane&7) is h-slice.
__global__ void __launch_bounds__(256) k_l1(
    const int* __restrict__ ei, const float* __restrict__ xg,
    const float* __restrict__ D1, const float* __restrict__ elen,
    const float* __restrict__ W1, const float* __restrict__ b1) {
    __shared__ __align__(16) float sW[640];
    __shared__ __align__(16) float sb[64];
    for (int i = threadIdx.x; i < 640; i += 256) sW[i] = W1[i];
    for (int i = threadIdx.x; i < 64; i += 256) sb[i] = b1[i];
    __syncthreads();
    int gw = (blockIdx.x * 256 + threadIdx.x) >> 5;
    int lane = threadIdx.x & 31;
    int sub = lane >> 3, h0 = (lane & 7) * 4;
    size_t e = (size_t)gw * 4 + sub;
    if (e >= EE) return;
    int src = ei[e], dst = ei[EE + e];
    float d = elen[e];
    float emb[10], ew;
    edge_basis(d, emb, ew);
    const float* Dp = D1 + e * 16;
    float4 R0 = *(const float4*)Dp;          // D1[e][0][0..3]
    float4 R2 = *(const float4*)(Dp + 8);    // D1[e][2][0..3]
    float xj = R0.x * __ldg(xg + src);       // D1[0][0] * x[src]
    float w0[4], w1[4];
    #pragma unroll
    for (int j = 0; j < 4; j++) { w0[j] = sb[h0 + j]; w1[j] = sb[32 + h0 + j]; }
    #pragma unroll
    for (int k = 0; k < 10; k++) {
        float ek = emb[k];
        float4 a = *(const float4*)&sW[k * 64 + h0];
        float4 b = *(const float4*)&sW[k * 64 + 32 + h0];
        w0[0] += ek * a.x; w0[1] += ek * a.y; w0[2] += ek * a.z; w0[3] += ek * a.w;
        w1[0] += ek * b.x; w1[1] += ek * b.y; w1[2] += ek * b.z; w1[3] += ek * b.w;
    }
    float o0[4], o2[4];
    #pragma unroll
    for (int j = 0; j < 4; j++) { o0[j] = xj * w0[j]; o2[j] = xj * w1[j]; }
    float D0m[4] = {R0.x, R0.y, R0.z, R0.w};
    float D2m[4] = {R2.x, R2.y, R2.z, R2.w};
    float* base = g_acc1 + (size_t)dst * 128 + h0;
    #pragma unroll
    for (int m = 0; m < 4; m++) {
        float v0 = ew * (D0m[m] * o0[0] + D2m[m] * o2[0]);
        float v1 = ew * (D0m[m] * o0[1] + D2m[m] * o2[1]);
        float v2 = ew * (D0m[m] * o0[2] + D2m[m] * o2[2]);
        float v3 = ew * (D0m[m] * o0[3] + D2m[m] * o2[3]);
        red4(base + m * 32, v0, v1, v2, v3);
    }
}

// -------- node mix: h = norm_act(dw(acc, si)) --------
__global__ void __launch_bounds__(256) k_node(int layer, const float* __restrict__ si) {
    __shared__ float s[2048];
    for (int i = threadIdx.x; i < 2048; i += 256) s[i] = si[i];
    __syncthreads();
    int n = (blockIdx.x * 256 + threadIdx.x) >> 5;
    int lane = threadIdx.x & 31;
    if (n >= NN) return;
    const float* hin = (layer == 1) ? g_acc1 : g_acc2;
    float* hout = (layer == 1) ? g_h1 : g_h2;
    const float* hb = hin + (size_t)n * 128;
    float hv0 = hb[lane], hv1 = hb[32 + lane], hv2 = hb[64 + lane], hv3 = hb[96 + lane];
    float g0 = 0.f, g1 = 0.f, g2 = 0.f, g3 = 0.f;
    #pragma unroll
    for (int c = 0; c < 32; c++) {
        float w0 = s[c * 32 + lane];
        float w1 = s[1024 + c * 32 + lane];
        g0 += __shfl_sync(0xffffffffu, hv0, c) * w0;
        g1 += __shfl_sync(0xffffffffu, hv1, c) * w1;
        g2 += __shfl_sync(0xffffffffu, hv2, c) * w1;
        g3 += __shfl_sync(0xffffffffu, hv3, c) * w1;
    }
    float n0 = sqrtf(g0 * g0 + 1e-8f);
    float n1 = sqrtf(g1 * g1 + g2 * g2 + g3 * g3 + 1e-8f);
    float f0 = sspf(n0) / n0;
    float f1 = sspf(n1) / n1;
    float* ho = hout + (size_t)n * 128;
    ho[lane] = g0 * f0;
    ho[32 + lane] = g1 * f1;
    ho[64 + lane] = g2 * f1;
    ho[96 + lane] = g3 * f1;
}

// -------- layer 2 edge kernel --------
__global__ void __launch_bounds__(256) k_l2(
    const int* __restrict__ ei, const float* __restrict__ D1,
    const float* __restrict__ elen,
    const float* __restrict__ W2, const float* __restrict__ b2) {
    __shared__ __align__(16) float sW[1920];
    __shared__ __align__(16) float sb[192];
    for (int i = threadIdx.x; i < 1920; i += 256) sW[i] = W2[i];
    for (int i = threadIdx.x; i < 192; i += 256) sb[i] = b2[i];
    __syncthreads();
    int gw = (blockIdx.x * 256 + threadIdx.x) >> 5;
    int lane = threadIdx.x & 31;
    int sub = lane >> 3, h0 = (lane & 7) * 4;
    size_t e = (size_t)gw * 4 + sub;
    if (e >= EE) return;
    int src = ei[e], dst = ei[EE + e];
    float d = elen[e];
    float emb[10], ew;
    edge_basis(d, emb, ew);
    float Dm[16];
    const float4* Dp = (const float4*)(D1 + e * 16);
    #pragma unroll
    for (int r = 0; r < 4; r++) {
        float4 v = Dp[r];
        Dm[r * 4] = v.x; Dm[r * 4 + 1] = v.y; Dm[r * 4 + 2] = v.z; Dm[r * 4 + 3] = v.w;
    }
    float hs[4][4];
    const float* hb = g_h1 + (size_t)src * 128 + h0;
    #pragma unroll
    for (int n = 0; n < 4; n++) {
        float4 v = *(const float4*)(hb + n * 32);
        hs[n][0] = v.x; hs[n][1] = v.y; hs[n][2] = v.z; hs[n][3] = v.w;
    }
    float xj[4][4];
    #pragma unroll
    for (int m = 0; m < 4; m++) {
        #pragma unroll
        for (int j = 0; j < 4; j++)
            xj[m][j] = Dm[m * 4] * hs[0][j] + Dm[m * 4 + 1] * hs[1][j]
                     + Dm[m * 4 + 2] * hs[2][j] + Dm[m * 4 + 3] * hs[3][j];
    }
    float w[6][4];
    #pragma unroll
    for (int r = 0; r < 6; r++) {
        float4 bv = *(const float4*)&sb[r * 32 + h0];
        w[r][0] = bv.x; w[r][1] = bv.y; w[r][2] = bv.z; w[r][3] = bv.w;
    }
    #pragma unroll
    for (int k = 0; k < 10; k++) {
        float ek = emb[k];
        #pragma unroll
        for (int r = 0; r < 6; r++) {
            float4 wv = *(const float4*)&sW[k * 192 + r * 32 + h0];
            w[r][0] += ek * wv.x; w[r][1] += ek * wv.y;
            w[r][2] += ek * wv.z; w[r][3] += ek * wv.w;
        }
    }
    float o[4][4];
    #pragma unroll
    for (int j = 0; j < 4; j++) {
        o[0][j] = w[0][j] * xj[0][j] + w[2][j] * xj[2][j];
        o[2][j] = w[1][j] * xj[0][j] + w[3][j] * xj[2][j];
        o[3][j] = w[4][j] * xj[3][j] - w[5][j] * xj[1][j];
        o[1][j] = w[5][j] * xj[3][j] + w[4][j] * xj[1][j];
    }
    float* base = g_acc2 + (size_t)dst * 128 + h0;
    #pragma unroll
    for (int m = 0; m < 4; m++) {
        float v[4];
        #pragma unroll
        for (int j = 0; j < 4; j++)
            v[j] = ew * (Dm[m] * o[0][j] + Dm[4 + m] * o[1][j]
                       + Dm[8 + m] * o[2][j] + Dm[12 + m] * o[3][j]);
        red4(base + m * 32, v[0], v[1], v[2], v[3]);
    }
}

// -------- layer 3 edge kernel --------
__global__ void __launch_bounds__(256) k_l3(
    const int* __restrict__ ei, const float* __restrict__ D1,
    const float* __restrict__ elen,
    const float* __restrict__ W3, const float* __restrict__ b3) {
    __shared__ __align__(16) float sW[640];
    __shared__ __align__(16) float sb[64];
    for (int i = threadIdx.x; i < 640; i += 256) sW[i] = W3[i];
    for (int i = threadIdx.x; i < 64; i += 256) sb[i] = b3[i];
    __syncthreads();
    int gw = (blockIdx.x * 256 + threadIdx.x) >> 5;
    int lane = threadIdx.x & 31;
    int sub = lane >> 3, h0 = (lane & 7) * 4;
    size_t e = (size_t)gw * 4 + sub;
    if (e >= EE) return;
    int src = ei[e], dst = ei[EE + e];
    float d = elen[e];
    float emb[10], ew;
    edge_basis(d, emb, ew);
    const float* Dp = D1 + e * 16;
    float4 R0 = *(const float4*)Dp;         // D1 row 0
    float4 R2 = *(const float4*)(Dp + 8);   // D1 row 2
    float hs[4][4];
    const float* hb = g_h2 + (size_t)src * 128 + h0;
    #pragma unroll
    for (int n = 0; n < 4; n++) {
        float4 v = *(const float4*)(hb + n * 32);
        hs[n][0] = v.x; hs[n][1] = v.y; hs[n][2] = v.z; hs[n][3] = v.w;
    }
    float w0[4], w1[4];
    #pragma unroll
    for (int j = 0; j < 4; j++) { w0[j] = sb[h0 + j]; w1[j] = sb[32 + h0 + j]; }
    #pragma unroll
    for (int k = 0; k < 10; k++) {
        float ek = emb[k];
        float4 a = *(const float4*)&sW[k * 64 + h0];
        float4 b = *(const float4*)&sW[k * 64 + 32 + h0];
        w0[0] += ek * a.x; w0[1] += ek * a.y; w0[2] += ek * a.z; w0[3] += ek * a.w;
        w1[0] += ek * b.x; w1[1] += ek * b.y; w1[2] += ek * b.z; w1[3] += ek * b.w;
    }
    float v[4];
    float scale = R0.x * ew;   // D1[0][0] * cutoff
    #pragma unroll
    for (int j = 0; j < 4; j++) {
        float xj0 = R0.x * hs[0][j] + R0.y * hs[1][j] + R0.z * hs[2][j] + R0.w * hs[3][j];
        float xj2 = R2.x * hs[0][j] + R2.y * hs[1][j] + R2.z * hs[2][j] + R2.w * hs[3][j];
        float o0 = w0[j] * xj0 + w1[j] * xj2;
        v[j] = scale * o0;
    }
    red4(g_acc3 + (size_t)dst * 32 + h0, v[0], v[1], v[2], v[3]);
}

// -------- node 3: silu(acc3 @ si3) then pool by batch --------
__global__ void __launch_bounds__(256) k_node3(
    const float* __restrict__ si3, const int* __restrict__ batch) {
    __shared__ float s[1024];
    for (int i = threadIdx.x; i < 1024; i += 256) s[i] = si3[i];
    __syncthreads();
    int n = (blockIdx.x * 256 + threadIdx.x) >> 5;
    int lane = threadIdx.x & 31;
    if (n >= NN) return;
    float hv = g_acc3[(size_t)n * 32 + lane];
    float acc = 0.f;
    #pragma unroll
    for (int c = 0; c < 32; c++)
        acc += __shfl_sync(0xffffffffu, hv, c) * s[c * 32 + lane];
    float sl = acc / (1.0f + __expf(-acc));   // silu
    atomicAdd(&g_pool[batch[n] * 32 + lane], sl);
}

// -------- final: softmax(pool @ Wo + bo) --------
__global__ void k_final(const float* __restrict__ Wo, const float* __restrict__ bo,
                        float* __restrict__ out) {
    int g = threadIdx.x;
    if (g >= GG) return;
    float acc[8];
    #pragma unroll
    for (int o = 0; o < 8; o++) acc[o] = bo[o];
    for (int dd = 0; dd < 32; dd++) {
        float p = g_pool[g * 32 + dd];
        #pragma unroll
        for (int o = 0; o < 8; o++) acc[o] += p * Wo[dd * 8 + o];
    }
    float mx = acc[0];
    #pragma unroll
    for (int o = 1; o < 8; o++) mx = fmaxf(mx, acc[o]);
    float sum = 0.f;
    #pragma unroll
    for (int o = 0; o < 8; o++) { acc[o] = __expf(acc[o] - mx); sum += acc[o]; }
    float inv = 1.0f / sum;
    #pragma unroll
    for (int o = 0; o < 8; o++) out[g * 8 + o] = acc[o] * inv;
}

extern "C" void kernel_launch(void* const* d_in, const int* in_sizes, int n_in,
                              void* d_out, int out_size) {
    const float* x    = (const float*)d_in[0];
    const int*   ei   = (const int*)d_in[1];
    const float* D1   = (const float*)d_in[2];
    const float* elen = (const float*)d_in[3];
    const int*   batch= (const int*)d_in[4];
    const float* W1   = (const float*)d_in[5];
    const float* b1   = (const float*)d_in[6];
    const float* W2   = (const float*)d_in[7];
    const float* b2   = (const float*)d_in[8];
    const float* W3   = (const float*)d_in[9];
    const float* b3   = (const float*)d_in[10];
    const float* si1  = (const float*)d_in[11];
    const float* si2  = (const float*)d_in[12];
    const float* si3  = (const float*)d_in[13];
    const float* Wo   = (const float*)d_in[14];
    const float* bo   = (const float*)d_in[15];
    float* out = (float*)d_out;

    const int edge_blocks = 25000;   // (E/4 warps) / 8 warps per 256-thr block
    const int node_blocks = 6250;    // N warps / 8

    k_zero<<<1024, 256>>>();
    k_l1<<<edge_blocks, 256>>>(ei, x, D1, elen, W1, b1);
    k_node<<<node_blocks, 256>>>(1, si1);
    k_l2<<<edge_blocks, 256>>>(ei, D1, elen, W2, b2);
    k_node<<<node_blocks, 256>>>(2, si2);
    k_l3<<<edge_blocks, 256>>>(ei, D1, elen, W3, b3);
    k_node3<<<node_blocks, 256>>>(si3, batch);
    k_final<<<1, 64>>>(Wo, bo, out);
}

// round 2
// speedup vs baseline: 1.2092x; 1.2092x over previous
#include <cuda_runtime.h>
#include <math.h>

#define NN 50000
#define EE 800000
#define GG 64

// -------- scratch (device globals; allocation-free) --------
static __device__ float g_acc1[NN * 128];
static __device__ float g_h1[NN * 128];
static __device__ float g_acc2[NN * 128];
static __device__ float g_h2[NN * 128];
static __device__ float g_acc3[NN * 32];
static __device__ float g_pool[GG * 32];

// -------- helpers --------
__device__ __forceinline__ void red4(float* p, float a, float b, float c, float d) {
    asm volatile("red.global.add.v4.f32 [%0], {%1,%2,%3,%4};"
                 :: "l"(p), "f"(a), "f"(b), "f"(c), "f"(d) : "memory");
}

__device__ __forceinline__ float sspf(float x) {   // softplus(x) - ln2, x >= 0
    return x + log1pf(__expf(-x)) - 0.6931471805599453f;
}

__device__ __forceinline__ float cutoff(float d) {
    float u = d * (1.0f / 1.5f);
    float u2 = u * u, u3 = u2 * u, u6 = u3 * u3;
    float f = 1.0f - 28.0f * u6 + 48.0f * u6 * u - 21.0f * u6 * u2;
    return (u < 1.0f) ? f : 0.0f;
}

// -------- zero accumulators --------
__global__ void k_zero() {
    size_t i = (size_t)blockIdx.x * blockDim.x + threadIdx.x;
    size_t stride = (size_t)gridDim.x * blockDim.x;
    float4 z = make_float4(0.f, 0.f, 0.f, 0.f);
    for (size_t j = i; j < (size_t)NN * 32; j += stride) {
        ((float4*)g_acc1)[j] = z;
        ((float4*)g_acc2)[j] = z;
    }
    for (size_t j = i; j < (size_t)NN * 8; j += stride) ((float4*)g_acc3)[j] = z;
    for (size_t j = i; j < (size_t)GG * 8; j += stride) ((float4*)g_pool)[j] = z;
}

// ==================== layer 1 ====================
// warp = 8 edges: 4 groups of 8 lanes; each thread handles 2 edges (e0, e0+4),
// sharing the weight LDS between them.
__device__ __forceinline__ void l1_tail(
    size_t e, const float (&A)[4], const float (&B)[4], float ew,
    const int* __restrict__ ei, const float* __restrict__ xg,
    const float* __restrict__ D1, int h0) {
    int src = __ldg(ei + e), dst = __ldg(ei + EE + e);
    const float* Dp = D1 + e * 16;
    float4 R0 = __ldg((const float4*)Dp);        // D1 row 0
    float4 R2 = __ldg((const float4*)(Dp + 8));  // D1 row 2
    float xj = R0.x * __ldg(xg + src);
    float o0[4], o2[4];
    #pragma unroll
    for (int j = 0; j < 4; j++) { o0[j] = xj * A[j]; o2[j] = xj * B[j]; }
    float R0a[4] = {R0.x, R0.y, R0.z, R0.w};
    float R2a[4] = {R2.x, R2.y, R2.z, R2.w};
    float* base = g_acc1 + (size_t)dst * 128 + h0;
    #pragma unroll
    for (int m = 0; m < 4; m++) {
        red4(base + m * 32,
             ew * (R0a[m] * o0[0] + R2a[m] * o2[0]),
             ew * (R0a[m] * o0[1] + R2a[m] * o2[1]),
             ew * (R0a[m] * o0[2] + R2a[m] * o2[2]),
             ew * (R0a[m] * o0[3] + R2a[m] * o2[3]));
    }
}

__global__ void __launch_bounds__(256) k_l1(
    const int* __restrict__ ei, const float* __restrict__ xg,
    const float* __restrict__ D1, const float* __restrict__ elen,
    const float* __restrict__ W1, const float* __restrict__ b1) {
    __shared__ __align__(16) float sW[640];
    __shared__ __align__(16) float sb[64];
    for (int i = threadIdx.x; i < 640; i += 256) sW[i] = W1[i];
    for (int i = threadIdx.x; i < 64; i += 256) sb[i] = b1[i];
    __syncthreads();
    int gw = (blockIdx.x * 256 + threadIdx.x) >> 5;
    int lane = threadIdx.x & 31;
    int grp = lane >> 3, h0 = (lane & 7) * 4;
    size_t e0 = (size_t)gw * 8 + grp, e1 = e0 + 4;
    float d0 = __ldg(elen + e0), d1 = __ldg(elen + e1);
    float ew0 = cutoff(d0), ew1 = cutoff(d1);
    float A0[4], B0[4], A1[4], B1[4];
    #pragma unroll
    for (int j = 0; j < 4; j++) {
        float ba = sb[h0 + j], bb = sb[32 + h0 + j];
        A0[j] = A1[j] = ba; B0[j] = B1[j] = bb;
    }
    #pragma unroll
    for (int k = 0; k < 10; k++) {
        float mu = 0.7f + (float)k * (1.0f / 9.0f);
        float t0 = d0 - mu, t1 = d1 - mu;
        float g0 = __expf(-t0 * t0 * 50.0f);
        float g1 = __expf(-t1 * t1 * 50.0f);
        float4 wa = *(const float4*)&sW[k * 64 + h0];
        float4 wb = *(const float4*)&sW[k * 64 + 32 + h0];
        A0[0] += g0 * wa.x; A0[1] += g0 * wa.y; A0[2] += g0 * wa.z; A0[3] += g0 * wa.w;
        B0[0] += g0 * wb.x; B0[1] += g0 * wb.y; B0[2] += g0 * wb.z; B0[3] += g0 * wb.w;
        A1[0] += g1 * wa.x; A1[1] += g1 * wa.y; A1[2] += g1 * wa.z; A1[3] += g1 * wa.w;
        B1[0] += g1 * wb.x; B1[1] += g1 * wb.y; B1[2] += g1 * wb.z; B1[3] += g1 * wb.w;
    }
    l1_tail(e0, A0, B0, ew0, ei, xg, D1, h0);
    l1_tail(e1, A1, B1, ew1, ei, xg, D1, h0);
}

// ==================== node mix ====================
__global__ void __launch_bounds__(256) k_node(int layer, const float* __restrict__ si) {
    __shared__ float s[2048];
    for (int i = threadIdx.x; i < 2048; i += 256) s[i] = si[i];
    __syncthreads();
    int n = (blockIdx.x * 256 + threadIdx.x) >> 5;
    int lane = threadIdx.x & 31;
    if (n >= NN) return;
    const float* hin = (layer == 1) ? g_acc1 : g_acc2;
    float* hout = (layer == 1) ? g_h1 : g_h2;
    const float* hb = hin + (size_t)n * 128;
    float hv0 = hb[lane], hv1 = hb[32 + lane], hv2 = hb[64 + lane], hv3 = hb[96 + lane];
    float g0 = 0.f, g1 = 0.f, g2 = 0.f, g3 = 0.f;
    #pragma unroll
    for (int c = 0; c < 32; c++) {
        float w0 = s[c * 32 + lane];
        float w1 = s[1024 + c * 32 + lane];
        g0 += __shfl_sync(0xffffffffu, hv0, c) * w0;
        g1 += __shfl_sync(0xffffffffu, hv1, c) * w1;
        g2 += __shfl_sync(0xffffffffu, hv2, c) * w1;
        g3 += __shfl_sync(0xffffffffu, hv3, c) * w1;
    }
    float n0 = sqrtf(g0 * g0 + 1e-8f);
    float n1 = sqrtf(g1 * g1 + g2 * g2 + g3 * g3 + 1e-8f);
    float f0 = sspf(n0) / n0;
    float f1 = sspf(n1) / n1;
    float* ho = hout + (size_t)n * 128;
    ho[lane] = g0 * f0;
    ho[32 + lane] = g1 * f1;
    ho[64 + lane] = g2 * f1;
    ho[96 + lane] = g3 * f1;
}

// ==================== layer 2 ====================
__device__ __forceinline__ void l2_tail(
    size_t e, const float (&w)[24], float ew,
    const int* __restrict__ ei, const float* __restrict__ D1, int h0) {
    int src = __ldg(ei + e), dst = __ldg(ei + EE + e);
    float Dm[16];
    const float4* Dp = (const float4*)(D1 + e * 16);
    #pragma unroll
    for (int r = 0; r < 4; r++) {
        float4 v = __ldg(Dp + r);
        Dm[r * 4] = v.x; Dm[r * 4 + 1] = v.y; Dm[r * 4 + 2] = v.z; Dm[r * 4 + 3] = v.w;
    }
    float hs[4][4];
    const float* hb = g_h1 + (size_t)src * 128 + h0;
    #pragma unroll
    for (int n = 0; n < 4; n++) {
        float4 v = __ldg((const float4*)(hb + n * 32));
        hs[n][0] = v.x; hs[n][1] = v.y; hs[n][2] = v.z; hs[n][3] = v.w;
    }
    float xj[4][4];
    #pragma unroll
    for (int m = 0; m < 4; m++) {
        #pragma unroll
        for (int j = 0; j < 4; j++)
            xj[m][j] = Dm[m * 4] * hs[0][j] + Dm[m * 4 + 1] * hs[1][j]
                     + Dm[m * 4 + 2] * hs[2][j] + Dm[m * 4 + 3] * hs[3][j];
    }
    float o[4][4];
    #pragma unroll
    for (int j = 0; j < 4; j++) {
        o[0][j] = w[0 * 4 + j] * xj[0][j] + w[2 * 4 + j] * xj[2][j];
        o[2][j] = w[1 * 4 + j] * xj[0][j] + w[3 * 4 + j] * xj[2][j];
        o[3][j] = w[4 * 4 + j] * xj[3][j] - w[5 * 4 + j] * xj[1][j];
        o[1][j] = w[5 * 4 + j] * xj[3][j] + w[4 * 4 + j] * xj[1][j];
    }
    float* base = g_acc2 + (size_t)dst * 128 + h0;
    #pragma unroll
    for (int m = 0; m < 4; m++) {
        red4(base + m * 32,
             ew * (Dm[m] * o[0][0] + Dm[4 + m] * o[1][0] + Dm[8 + m] * o[2][0] + Dm[12 + m] * o[3][0]),
             ew * (Dm[m] * o[0][1] + Dm[4 + m] * o[1][1] + Dm[8 + m] * o[2][1] + Dm[12 + m] * o[3][1]),
             ew * (Dm[m] * o[0][2] + Dm[4 + m] * o[1][2] + Dm[8 + m] * o[2][2] + Dm[12 + m] * o[3][2]),
             ew * (Dm[m] * o[0][3] + Dm[4 + m] * o[1][3] + Dm[8 + m] * o[2][3] + Dm[12 + m] * o[3][3]));
    }
}

__global__ void __launch_bounds__(256) k_l2(
    const int* __restrict__ ei, const float* __restrict__ D1,
    const float* __restrict__ elen,
    const float* __restrict__ W2, const float* __restrict__ b2) {
    __shared__ __align__(16) float sW[1920];
    __shared__ __align__(16) float sb[192];
    for (int i = threadIdx.x; i < 1920; i += 256) sW[i] = W2[i];
    for (int i = threadIdx.x; i < 192; i += 256) sb[i] = b2[i];
    __syncthreads();
    int gw = (blockIdx.x * 256 + threadIdx.x) >> 5;
    int lane = threadIdx.x & 31;
    int grp = lane >> 3, h0 = (lane & 7) * 4;
    size_t e0 = (size_t)gw * 8 + grp, e1 = e0 + 4;
    float d0 = __ldg(elen + e0), d1 = __ldg(elen + e1);
    float ew0 = cutoff(d0), ew1 = cutoff(d1);
    float w0[24], w1[24];
    #pragma unroll
    for (int r = 0; r < 6; r++) {
        float4 bv = *(const float4*)&sb[r * 32 + h0];
        w0[r * 4 + 0] = w1[r * 4 + 0] = bv.x;
        w0[r * 4 + 1] = w1[r * 4 + 1] = bv.y;
        w0[r * 4 + 2] = w1[r * 4 + 2] = bv.z;
        w0[r * 4 + 3] = w1[r * 4 + 3] = bv.w;
    }
    #pragma unroll
    for (int k = 0; k < 10; k++) {
        float mu = 0.7f + (float)k * (1.0f / 9.0f);
        float t0 = d0 - mu, t1 = d1 - mu;
        float g0 = __expf(-t0 * t0 * 50.0f);
        float g1 = __expf(-t1 * t1 * 50.0f);
        #pragma unroll
        for (int r = 0; r < 6; r++) {
            float4 wv = *(const float4*)&sW[k * 192 + r * 32 + h0];
            w0[r * 4 + 0] += g0 * wv.x; w0[r * 4 + 1] += g0 * wv.y;
            w0[r * 4 + 2] += g0 * wv.z; w0[r * 4 + 3] += g0 * wv.w;
            w1[r * 4 + 0] += g1 * wv.x; w1[r * 4 + 1] += g1 * wv.y;
            w1[r * 4 + 2] += g1 * wv.z; w1[r * 4 + 3] += g1 * wv.w;
        }
    }
    l2_tail(e0, w0, ew0, ei, D1, h0);
    l2_tail(e1, w1, ew1, ei, D1, h0);
}

// ==================== layer 3 ====================
__device__ __forceinline__ void l3_tail(
    size_t e, const float (&A)[4], const float (&B)[4], float ew,
    const int* __restrict__ ei, const float* __restrict__ D1, int h0) {
    int src = __ldg(ei + e), dst = __ldg(ei + EE + e);
    const float* Dp = D1 + e * 16;
    float4 R0 = __ldg((const float4*)Dp);
    float4 R2 = __ldg((const float4*)(Dp + 8));
    float hs[4][4];
    const float* hb = g_h2 + (size_t)src * 128 + h0;
    #pragma unroll
    for (int n = 0; n < 4; n++) {
        float4 v = __ldg((const float4*)(hb + n * 32));
        hs[n][0] = v.x; hs[n][1] = v.y; hs[n][2] = v.z; hs[n][3] = v.w;
    }
    float v[4];
    float scale = R0.x * ew;
    #pragma unroll
    for (int j = 0; j < 4; j++) {
        float xj0 = R0.x * hs[0][j] + R0.y * hs[1][j] + R0.z * hs[2][j] + R0.w * hs[3][j];
        float xj2 = R2.x * hs[0][j] + R2.y * hs[1][j] + R2.z * hs[2][j] + R2.w * hs[3][j];
        v[j] = scale * (A[j] * xj0 + B[j] * xj2);
    }
    red4(g_acc3 + (size_t)dst * 32 + h0, v[0], v[1], v[2], v[3]);
}

__global__ void __launch_bounds__(256) k_l3(
    const int* __restrict__ ei, const float* __restrict__ D1,
    const float* __restrict__ elen,
    const float* __restrict__ W3, const float* __restrict__ b3) {
    __shared__ __align__(16) float sW[640];
    __shared__ __align__(16) float sb[64];
    for (int i = threadIdx.x; i < 640; i += 256) sW[i] = W3[i];
    for (int i = threadIdx.x; i < 64; i += 256) sb[i] = b3[i];
    __syncthreads();
    int gw = (blockIdx.x * 256 + threadIdx.x) >> 5;
    int lane = threadIdx.x & 31;
    int grp = lane >> 3, h0 = (lane & 7) * 4;
    size_t e0 = (size_t)gw * 8 + grp, e1 = e0 + 4;
    float d0 = __ldg(elen + e0), d1 = __ldg(elen + e1);
    float ew0 = cutoff(d0), ew1 = cutoff(d1);
    float A0[4], B0[4], A1[4], B1[4];
    #pragma unroll
    for (int j = 0; j < 4; j++) {
        float ba = sb[h0 + j], bb = sb[32 + h0 + j];
        A0[j] = A1[j] = ba; B0[j] = B1[j] = bb;
    }
    #pragma unroll
    for (int k = 0; k < 10; k++) {
        float mu = 0.7f + (float)k * (1.0f / 9.0f);
        float t0 = d0 - mu, t1 = d1 - mu;
        float g0 = __expf(-t0 * t0 * 50.0f);
        float g1 = __expf(-t1 * t1 * 50.0f);
        float4 wa = *(const float4*)&sW[k * 64 + h0];
        float4 wb = *(const float4*)&sW[k * 64 + 32 + h0];
        A0[0] += g0 * wa.x; A0[1] += g0 * wa.y; A0[2] += g0 * wa.z; A0[3] += g0 * wa.w;
        B0[0] += g0 * wb.x; B0[1] += g0 * wb.y; B0[2] += g0 * wb.z; B0[3] += g0 * wb.w;
        A1[0] += g1 * wa.x; A1[1] += g1 * wa.y; A1[2] += g1 * wa.z; A1[3] += g1 * wa.w;
        B1[0] += g1 * wb.x; B1[1] += g1 * wb.y; B1[2] += g1 * wb.z; B1[3] += g1 * wb.w;
    }
    l3_tail(e0, A0, B0, ew0, ei, D1, h0);
    l3_tail(e1, A1, B1, ew1, ei, D1, h0);
}

// ==================== node 3 + pool ====================
__global__ void __launch_bounds__(256) k_node3(
    const float* __restrict__ si3, const int* __restrict__ batch) {
    __shared__ float s[1024];
    for (int i = threadIdx.x; i < 1024; i += 256) s[i] = si3[i];
    __syncthreads();
    int n = (blockIdx.x * 256 + threadIdx.x) >> 5;
    int lane = threadIdx.x & 31;
    if (n >= NN) return;
    float hv = g_acc3[(size_t)n * 32 + lane];
    float acc = 0.f;
    #pragma unroll
    for (int c = 0; c < 32; c++)
        acc += __shfl_sync(0xffffffffu, hv, c) * s[c * 32 + lane];
    float sl = acc / (1.0f + __expf(-acc));
    atomicAdd(&g_pool[batch[n] * 32 + lane], sl);
}

// ==================== final ====================
__global__ void k_final(const float* __restrict__ Wo, const float* __restrict__ bo,
                        float* __restrict__ out) {
    int g = threadIdx.x;
    if (g >= GG) return;
    float acc[8];
    #pragma unroll
    for (int o = 0; o < 8; o++) acc[o] = bo[o];
    for (int dd = 0; dd < 32; dd++) {
        float p = g_pool[g * 32 + dd];
        #pragma unroll
        for (int o = 0; o < 8; o++) acc[o] += p * Wo[dd * 8 + o];
    }
    float mx = acc[0];
    #pragma unroll
    for (int o = 1; o < 8; o++) mx = fmaxf(mx, acc[o]);
    float sum = 0.f;
    #pragma unroll
    for (int o = 0; o < 8; o++) { acc[o] = __expf(acc[o] - mx); sum += acc[o]; }
    float inv = 1.0f / sum;
    #pragma unroll
    for (int o = 0; o < 8; o++) out[g * 8 + o] = acc[o] * inv;
}

extern "C" void kernel_launch(void* const* d_in, const int* in_sizes, int n_in,
                              void* d_out, int out_size) {
    const float* x    = (const float*)d_in[0];
    const int*   ei   = (const int*)d_in[1];
    const float* D1   = (const float*)d_in[2];
    const float* elen = (const float*)d_in[3];
    const int*   batch= (const int*)d_in[4];
    const float* W1   = (const float*)d_in[5];
    const float* b1   = (const float*)d_in[6];
    const float* W2   = (const float*)d_in[7];
    const float* b2   = (const float*)d_in[8];
    const float* W3   = (const float*)d_in[9];
    const float* b3   = (const float*)d_in[10];
    const float* si1  = (const float*)d_in[11];
    const float* si2  = (const float*)d_in[12];
    const float* si3  = (const float*)d_in[13];
    const float* Wo   = (const float*)d_in[14];
    const float* bo   = (const float*)d_in[15];
    float* out = (float*)d_out;

    const int edge_blocks = EE / 64;   // 8 warps/block * 8 edges/warp
    const int node_blocks = 6250;      // N warps / 8

    k_zero<<<1024, 256>>>();
    k_l1<<<edge_blocks, 256>>>(ei, x, D1, elen, W1, b1);
    k_node<<<node_blocks, 256>>>(1, si1);
    k_l2<<<edge_blocks, 256>>>(ei, D1, elen, W2, b2);
    k_node<<<node_blocks, 256>>>(2, si2);
    k_l3<<<edge_blocks, 256>>>(ei, D1, elen, W3, b3);
    k_node3<<<node_blocks, 256>>>(si3, batch);
    k_final<<<1, 64>>>(Wo, bo, out);
}

// round 4
// speedup vs baseline: 1.2595x; 1.0416x over previous
#include <cuda_runtime.h>
#include <math.h>

#define NN 50000
#define EE 800000
#define GG 64

typedef unsigned long long u64;

// -------- scratch (device globals; allocation-free) --------
static __device__ float g_acc1[NN * 128];
static __device__ float g_h1[NN * 128];
static __device__ float g_acc2[NN * 128];
static __device__ float g_h2[NN * 128];
static __device__ float g_acc3[NN * 32];
static __device__ float g_pool[GG * 32];

// -------- packed f32x2 helpers (Blackwell) --------
__device__ __forceinline__ u64 pk2(float lo, float hi) {
    u64 r; asm("mov.b64 %0,{%1,%2};" : "=l"(r) : "f"(lo), "f"(hi)); return r;
}
__device__ __forceinline__ u64 pks(float s) { return pk2(s, s); }
__device__ __forceinline__ void up2(u64 v, float& lo, float& hi) {
    asm("mov.b64 {%0,%1},%2;" : "=f"(lo), "=f"(hi) : "l"(v));
}
__device__ __forceinline__ u64 f2fma(u64 a, u64 b, u64 c) {
    u64 d; asm("fma.rn.f32x2 %0,%1,%2,%3;" : "=l"(d) : "l"(a), "l"(b), "l"(c)); return d;
}
__device__ __forceinline__ u64 f2mul(u64 a, u64 b) {
    u64 d; asm("mul.rn.f32x2 %0,%1,%2;" : "=l"(d) : "l"(a), "l"(b)); return d;
}
__device__ __forceinline__ u64 f2neg(u64 a) { return a ^ 0x8000000080000000ULL; }

// -------- misc helpers --------
__device__ __forceinline__ void red4(float* p, float a, float b, float c, float d) {
    asm volatile("red.global.add.v4.f32 [%0], {%1,%2,%3,%4};"
                 :: "l"(p), "f"(a), "f"(b), "f"(c), "f"(d) : "memory");
}
__device__ __forceinline__ void red4u(float* p, u64 lo, u64 hi) {
    float a, b, c, d;
    up2(lo, a, b); up2(hi, c, d);
    red4(p, a, b, c, d);
}

__device__ __forceinline__ float sspf(float x) {   // softplus(x) - ln2, x >= 0
    return x + log1pf(__expf(-x)) - 0.6931471805599453f;
}

__device__ __forceinline__ float cutoff(float d) {
    float u = d * (1.0f / 1.5f);
    float u2 = u * u, u3 = u2 * u, u6 = u3 * u3;
    float f = 1.0f - 28.0f * u6 + 48.0f * u6 * u - 21.0f * u6 * u2;
    return (u < 1.0f) ? f : 0.0f;
}

// -------- zero accumulators --------
__global__ void k_zero() {
    size_t i = (size_t)blockIdx.x * blockDim.x + threadIdx.x;
    size_t stride = (size_t)gridDim.x * blockDim.x;
    float4 z = make_float4(0.f, 0.f, 0.f, 0.f);
    for (size_t j = i; j < (size_t)NN * 32; j += stride) {
        ((float4*)g_acc1)[j] = z;
        ((float4*)g_acc2)[j] = z;
    }
    for (size_t j = i; j < (size_t)NN * 8; j += stride) ((float4*)g_acc3)[j] = z;
    for (size_t j = i; j < (size_t)GG * 8; j += stride) ((float4*)g_pool)[j] = z;
}

// ==================== layer 1 ====================
// warp = 8 edges: 4 groups of 8 lanes; each thread handles 2 edges (e0, e0+4).
__device__ __forceinline__ void l1_tail(
    size_t e, const u64 (&A)[2], const u64 (&B)[2], float ew,
    const int* __restrict__ ei, const float* __restrict__ xg,
    const float* __restrict__ D1, int h0) {
    int src = __ldg(ei + e), dst = __ldg(ei + EE + e);
    const float* Dp = D1 + e * 16;
    float4 R0 = __ldg((const float4*)Dp);        // D1 row 0
    float4 R2 = __ldg((const float4*)(Dp + 8));  // D1 row 2
    float xs = ew * R0.x * __ldg(xg + src);      // ew * D1[0][0] * x[src]
    float R0a[4] = {R0.x, R0.y, R0.z, R0.w};
    float R2a[4] = {R2.x, R2.y, R2.z, R2.w};
    float* base = g_acc1 + (size_t)dst * 128 + h0;
    #pragma unroll
    for (int m = 0; m < 4; m++) {
        u64 ap = pks(xs * R0a[m]);
        u64 bp = pks(xs * R2a[m]);
        u64 vlo = f2fma(bp, B[0], f2mul(ap, A[0]));
        u64 vhi = f2fma(bp, B[1], f2mul(ap, A[1]));
        red4u(base + m * 32, vlo, vhi);
    }
}

__global__ void __launch_bounds__(256) k_l1(
    const int* __restrict__ ei, const float* __restrict__ xg,
    const float* __restrict__ D1, const float* __restrict__ elen,
    const float* __restrict__ W1, const float* __restrict__ b1) {
    __shared__ __align__(16) float sW[640];
    __shared__ __align__(16) float sb[64];
    for (int i = threadIdx.x; i < 640; i += 256) sW[i] = W1[i];
    for (int i = threadIdx.x; i < 64; i += 256) sb[i] = b1[i];
    __syncthreads();
    int gw = (blockIdx.x * 256 + threadIdx.x) >> 5;
    int lane = threadIdx.x & 31;
    int grp = lane >> 3, h0 = (lane & 7) * 4;
    size_t e0 = (size_t)gw * 8 + grp, e1 = e0 + 4;
    float d0 = __ldg(elen + e0), d1 = __ldg(elen + e1);
    float ew0 = cutoff(d0), ew1 = cutoff(d1);
    u64 A0[2], B0[2], A1[2], B1[2];
    {
        ulonglong2 ba = *(const ulonglong2*)&sb[h0];
        ulonglong2 bb = *(const ulonglong2*)&sb[32 + h0];
        A0[0] = A1[0] = ba.x; A0[1] = A1[1] = ba.y;
        B0[0] = B1[0] = bb.x; B0[1] = B1[1] = bb.y;
    }
    #pragma unroll
    for (int k = 0; k < 10; k++) {
        float mu = 0.7f + (float)k * (1.0f / 9.0f);
        float t0 = d0 - mu, t1 = d1 - mu;
        u64 g0p = pks(__expf(-t0 * t0 * 50.0f));
        u64 g1p = pks(__expf(-t1 * t1 * 50.0f));
        ulonglong2 wa = *(const ulonglong2*)&sW[k * 64 + h0];
        ulonglong2 wb = *(const ulonglong2*)&sW[k * 64 + 32 + h0];
        A0[0] = f2fma(g0p, wa.x, A0[0]); A0[1] = f2fma(g0p, wa.y, A0[1]);
        B0[0] = f2fma(g0p, wb.x, B0[0]); B0[1] = f2fma(g0p, wb.y, B0[1]);
        A1[0] = f2fma(g1p, wa.x, A1[0]); A1[1] = f2fma(g1p, wa.y, A1[1]);
        B1[0] = f2fma(g1p, wb.x, B1[0]); B1[1] = f2fma(g1p, wb.y, B1[1]);
    }
    l1_tail(e0, A0, B0, ew0, ei, xg, D1, h0);
    l1_tail(e1, A1, B1, ew1, ei, xg, D1, h0);
}

// ==================== node mix ====================
__global__ void __launch_bounds__(256) k_node(int layer, const float* __restrict__ si) {
    __shared__ float s[2048];
    for (int i = threadIdx.x; i < 2048; i += 256) s[i] = si[i];
    __syncthreads();
    int n = (blockIdx.x * 256 + threadIdx.x) >> 5;
    int lane = threadIdx.x & 31;
    if (n >= NN) return;
    const float* hin = (layer == 1) ? g_acc1 : g_acc2;
    float* hout = (layer == 1) ? g_h1 : g_h2;
    const float* hb = hin + (size_t)n * 128;
    float hv0 = hb[lane], hv1 = hb[32 + lane], hv2 = hb[64 + lane], hv3 = hb[96 + lane];
    float g0 = 0.f, g3 = 0.f;
    u64 g12 = 0;
    #pragma unroll
    for (int c = 0; c < 32; c++) {
        float w0 = s[c * 32 + lane];
        float w1 = s[1024 + c * 32 + lane];
        float a1 = __shfl_sync(0xffffffffu, hv1, c);
        float a2 = __shfl_sync(0xffffffffu, hv2, c);
        float a3 = __shfl_sync(0xffffffffu, hv3, c);
        g0 += __shfl_sync(0xffffffffu, hv0, c) * w0;
        g12 = f2fma(pks(w1), pk2(a1, a2), g12);
        g3 += w1 * a3;
    }
    float g1, g2;
    up2(g12, g1, g2);
    float n0 = sqrtf(g0 * g0 + 1e-8f);
    float n1 = sqrtf(g1 * g1 + g2 * g2 + g3 * g3 + 1e-8f);
    float f0 = sspf(n0) / n0;
    float f1 = sspf(n1) / n1;
    float* ho = hout + (size_t)n * 128;
    ho[lane] = g0 * f0;
    ho[32 + lane] = g1 * f1;
    ho[64 + lane] = g2 * f1;
    ho[96 + lane] = g3 * f1;
}

// ==================== layer 2 ====================
__device__ __forceinline__ void l2_tail(
    size_t e, const u64 (&w)[12], float ew,
    const int* __restrict__ ei, const float* __restrict__ D1, int h0) {
    int src = __ldg(ei + e), dst = __ldg(ei + EE + e);
    float Dm[16];
    const float4* Dp = (const float4*)(D1 + e * 16);
    #pragma unroll
    for (int r = 0; r < 4; r++) {
        float4 v = __ldg(Dp + r);
        Dm[r * 4] = v.x; Dm[r * 4 + 1] = v.y; Dm[r * 4 + 2] = v.z; Dm[r * 4 + 3] = v.w;
    }
    u64 hs[4][2];
    const float* hb = g_h1 + (size_t)src * 128 + h0;
    #pragma unroll
    for (int n = 0; n < 4; n++) {
        ulonglong2 v = __ldg((const ulonglong2*)(hb + n * 32));
        hs[n][0] = v.x; hs[n][1] = v.y;
    }
    // xj[m] = sum_n D[m][n] * hs[n]
    u64 xj[4][2];
    #pragma unroll
    for (int m = 0; m < 4; m++) {
        u64 p0 = pks(Dm[m * 4]), p1 = pks(Dm[m * 4 + 1]);
        u64 p2 = pks(Dm[m * 4 + 2]), p3 = pks(Dm[m * 4 + 3]);
        #pragma unroll
        for (int p = 0; p < 2; p++) {
            u64 t = f2mul(p0, hs[0][p]);
            t = f2fma(p1, hs[1][p], t);
            t = f2fma(p2, hs[2][p], t);
            xj[m][p] = f2fma(p3, hs[3][p], t);
        }
    }
    u64 o[4][2];
    u64 ewp = pks(ew);
    #pragma unroll
    for (int p = 0; p < 2; p++) {
        u64 t0 = f2fma(w[2 * 2 + p], xj[2][p], f2mul(w[0 * 2 + p], xj[0][p]));
        u64 t2 = f2fma(w[3 * 2 + p], xj[2][p], f2mul(w[1 * 2 + p], xj[0][p]));
        u64 t3 = f2fma(w[4 * 2 + p], xj[3][p], f2neg(f2mul(w[5 * 2 + p], xj[1][p])));
        u64 t1 = f2fma(w[5 * 2 + p], xj[3][p], f2mul(w[4 * 2 + p], xj[1][p]));
        o[0][p] = f2mul(t0, ewp);
        o[1][p] = f2mul(t1, ewp);
        o[2][p] = f2mul(t2, ewp);
        o[3][p] = f2mul(t3, ewp);
    }
    // out[m] = sum_i D[i][m] * o[i]
    float* base = g_acc2 + (size_t)dst * 128 + h0;
    #pragma unroll
    for (int m = 0; m < 4; m++) {
        u64 q0 = pks(Dm[m]), q1 = pks(Dm[4 + m]);
        u64 q2 = pks(Dm[8 + m]), q3 = pks(Dm[12 + m]);
        u64 vlo = f2mul(q0, o[0][0]);
        vlo = f2fma(q1, o[1][0], vlo);
        vlo = f2fma(q2, o[2][0], vlo);
        vlo = f2fma(q3, o[3][0], vlo);
        u64 vhi = f2mul(q0, o[0][1]);
        vhi = f2fma(q1, o[1][1], vhi);
        vhi = f2fma(q2, o[2][1], vhi);
        vhi = f2fma(q3, o[3][1], vhi);
        red4u(base + m * 32, vlo, vhi);
    }
}

__global__ void __launch_bounds__(256) k_l2(
    const int* __restrict__ ei, const float* __restrict__ D1,
    const float* __restrict__ elen,
    const float* __restrict__ W2, const float* __restrict__ b2) {
    __shared__ __align__(16) float sW[1920];
    __shared__ __align__(16) float sb[192];
    for (int i = threadIdx.x; i < 1920; i += 256) sW[i] = W2[i];
    for (int i = threadIdx.x; i < 192; i += 256) sb[i] = b2[i];
    __syncthreads();
    int gw = (blockIdx.x * 256 + threadIdx.x) >> 5;
    int lane = threadIdx.x & 31;
    int grp = lane >> 3, h0 = (lane & 7) * 4;
    size_t e0 = (size_t)gw * 8 + grp, e1 = e0 + 4;
    float d0 = __ldg(elen + e0), d1 = __ldg(elen + e1);
    float ew0 = cutoff(d0), ew1 = cutoff(d1);
    u64 w0[12], w1[12];
    #pragma unroll
    for (int r = 0; r < 6; r++) {
        ulonglong2 bv = *(const ulonglong2*)&sb[r * 32 + h0];
        w0[r * 2] = w1[r * 2] = bv.x;
        w0[r * 2 + 1] = w1[r * 2 + 1] = bv.y;
    }
    #pragma unroll
    for (int k = 0; k < 10; k++) {
        float mu = 0.7f + (float)k * (1.0f / 9.0f);
        float t0 = d0 - mu, t1 = d1 - mu;
        u64 g0p = pks(__expf(-t0 * t0 * 50.0f));
        u64 g1p = pks(__expf(-t1 * t1 * 50.0f));
        #pragma unroll
        for (int r = 0; r < 6; r++) {
            ulonglong2 wv = *(const ulonglong2*)&sW[k * 192 + r * 32 + h0];
            w0[r * 2] = f2fma(g0p, wv.x, w0[r * 2]);
            w0[r * 2 + 1] = f2fma(g0p, wv.y, w0[r * 2 + 1]);
            w1[r * 2] = f2fma(g1p, wv.x, w1[r * 2]);
            w1[r * 2 + 1] = f2fma(g1p, wv.y, w1[r * 2 + 1]);
        }
    }
    l2_tail(e0, w0, ew0, ei, D1, h0);
    l2_tail(e1, w1, ew1, ei, D1, h0);
}

// ==================== layer 3 ====================
__device__ __forceinline__ void l3_tail(
    size_t e, const u64 (&A)[2], const u64 (&B)[2], float ew,
    const int* __restrict__ ei, const float* __restrict__ D1, int h0) {
    int src = __ldg(ei + e), dst = __ldg(ei + EE + e);
    const float* Dp = D1 + e * 16;
    float4 R0 = __ldg((const float4*)Dp);
    float4 R2 = __ldg((const float4*)(Dp + 8));
    u64 hs[4][2];
    const float* hb = g_h2 + (size_t)src * 128 + h0;
    #pragma unroll
    for (int n = 0; n < 4; n++) {
        ulonglong2 v = __ldg((const ulonglong2*)(hb + n * 32));
        hs[n][0] = v.x; hs[n][1] = v.y;
    }
    float R0a[4] = {R0.x, R0.y, R0.z, R0.w};
    float R2a[4] = {R2.x, R2.y, R2.z, R2.w};
    u64 xj0[2], xj2[2];
    #pragma unroll
    for (int p = 0; p < 2; p++) {
        u64 t = f2mul(pks(R0a[0]), hs[0][p]);
        t = f2fma(pks(R0a[1]), hs[1][p], t);
        t = f2fma(pks(R0a[2]), hs[2][p], t);
        xj0[p] = f2fma(pks(R0a[3]), hs[3][p], t);
        u64 s = f2mul(pks(R2a[0]), hs[0][p]);
        s = f2fma(pks(R2a[1]), hs[1][p], s);
        s = f2fma(pks(R2a[2]), hs[2][p], s);
        xj2[p] = f2fma(pks(R2a[3]), hs[3][p], s);
    }
    u64 sc = pks(R0.x * ew);
    u64 vlo = f2mul(sc, f2fma(B[0], xj2[0], f2mul(A[0], xj0[0])));
    u64 vhi = f2mul(sc, f2fma(B[1], xj2[1], f2mul(A[1], xj0[1])));
    red4u(g_acc3 + (size_t)dst * 32 + h0, vlo, vhi);
}

__global__ void __launch_bounds__(256) k_l3(
    const int* __restrict__ ei, const float* __restrict__ D1,
    const float* __restrict__ elen,
    const float* __restrict__ W3, const float* __restrict__ b3) {
    __shared__ __align__(16) float sW[640];
    __shared__ __align__(16) float sb[64];
    for (int i = threadIdx.x; i < 640; i += 256) sW[i] = W3[i];
    for (int i = threadIdx.x; i < 64; i += 256) sb[i] = b3[i];
    __syncthreads();
    int gw = (blockIdx.x * 256 + threadIdx.x) >> 5;
    int lane = threadIdx.x & 31;
    int grp = lane >> 3, h0 = (lane & 7) * 4;
    size_t e0 = (size_t)gw * 8 + grp, e1 = e0 + 4;
    float d0 = __ldg(elen + e0), d1 = __ldg(elen + e1);
    float ew0 = cutoff(d0), ew1 = cutoff(d1);
    u64 A0[2], B0[2], A1[2], B1[2];
    {
        ulonglong2 ba = *(const ulonglong2*)&sb[h0];
        ulonglong2 bb = *(const ulonglong2*)&sb[32 + h0];
        A0[0] = A1[0] = ba.x; A0[1] = A1[1] = ba.y;
        B0[0] = B1[0] = bb.x; B0[1] = B1[1] = bb.y;
    }
    #pragma unroll
    for (int k = 0; k < 10; k++) {
        float mu = 0.7f + (float)k * (1.0f / 9.0f);
        float t0 = d0 - mu, t1 = d1 - mu;
        u64 g0p = pks(__expf(-t0 * t0 * 50.0f));
        u64 g1p = pks(__expf(-t1 * t1 * 50.0f));
        ulonglong2 wa = *(const ulonglong2*)&sW[k * 64 + h0];
        ulonglong2 wb = *(const ulonglong2*)&sW[k * 64 + 32 + h0];
        A0[0] = f2fma(g0p, wa.x, A0[0]); A0[1] = f2fma(g0p, wa.y, A0[1]);
        B0[0] = f2fma(g0p, wb.x, B0[0]); B0[1] = f2fma(g0p, wb.y, B0[1]);
        A1[0] = f2fma(g1p, wa.x, A1[0]); A1[1] = f2fma(g1p, wa.y, A1[1]);
        B1[0] = f2fma(g1p, wb.x, B1[0]); B1[1] = f2fma(g1p, wb.y, B1[1]);
    }
    l3_tail(e0, A0, B0, ew0, ei, D1, h0);
    l3_tail(e1, A1, B1, ew1, ei, D1, h0);
}

// ==================== node 3 + pool ====================
__global__ void __launch_bounds__(256) k_node3(
    const float* __restrict__ si3, const int* __restrict__ batch) {
    __shared__ float s[1024];
    for (int i = threadIdx.x; i < 1024; i += 256) s[i] = si3[i];
    __syncthreads();
    int n = (blockIdx.x * 256 + threadIdx.x) >> 5;
    int lane = threadIdx.x & 31;
    if (n >= NN) return;
    float hv = g_acc3[(size_t)n * 32 + lane];
    float acc = 0.f;
    #pragma unroll
    for (int c = 0; c < 32; c++)
        acc += __shfl_sync(0xffffffffu, hv, c) * s[c * 32 + lane];
    float sl = acc / (1.0f + __expf(-acc));
    atomicAdd(&g_pool[batch[n] * 32 + lane], sl);
}

// ==================== final ====================
__global__ void k_final(const float* __restrict__ Wo, const float* __restrict__ bo,
                        float* __restrict__ out) {
    int g = threadIdx.x;
    if (g >= GG) return;
    float acc[8];
    #pragma unroll
    for (int o = 0; o < 8; o++) acc[o] = bo[o];
    for (int dd = 0; dd < 32; dd++) {
        float p = g_pool[g * 32 + dd];
        #pragma unroll
        for (int o = 0; o < 8; o++) acc[o] += p * Wo[dd * 8 + o];
    }
    float mx = acc[0];
    #pragma unroll
    for (int o = 1; o < 8; o++) mx = fmaxf(mx, acc[o]);
    float sum = 0.f;
    #pragma unroll
    for (int o = 0; o < 8; o++) { acc[o] = __expf(acc[o] - mx); sum += acc[o]; }
    float inv = 1.0f / sum;
    #pragma unroll
    for (int o = 0; o < 8; o++) out[g * 8 + o] = acc[o] * inv;
}

extern "C" void kernel_launch(void* const* d_in, const int* in_sizes, int n_in,
                              void* d_out, int out_size) {
    const float* x    = (const float*)d_in[0];
    const int*   ei   = (const int*)d_in[1];
    const float* D1   = (const float*)d_in[2];
    const float* elen = (const float*)d_in[3];
    const int*   batch= (const int*)d_in[4];
    const float* W1   = (const float*)d_in[5];
    const float* b1   = (const float*)d_in[6];
    const float* W2   = (const float*)d_in[7];
    const float* b2   = (const float*)d_in[8];
    const float* W3   = (const float*)d_in[9];
    const float* b3   = (const float*)d_in[10];
    const float* si1  = (const float*)d_in[11];
    const float* si2  = (const float*)d_in[12];
    const float* si3  = (const float*)d_in[13];
    const float* Wo   = (const float*)d_in[14];
    const float* bo   = (const float*)d_in[15];
    float* out = (float*)d_out;

    const int edge_blocks = EE / 64;   // 8 warps/block * 8 edges/warp
    const int node_blocks = 6250;      // N warps / 8

    k_zero<<<1024, 256>>>();
    k_l1<<<edge_blocks, 256>>>(ei, x, D1, elen, W1, b1);
    k_node<<<node_blocks, 256>>>(1, si1);
    k_l2<<<edge_blocks, 256>>>(ei, D1, elen, W2, b2);
    k_node<<<node_blocks, 256>>>(2, si2);
    k_l3<<<edge_blocks, 256>>>(ei, D1, elen, W3, b3);
    k_node3<<<node_blocks, 256>>>(si3, batch);
    k_final<<<1, 64>>>(Wo, bo, out);
}